// round 15
// baseline (speedup 1.0000x reference)
#include <cuda_runtime.h>
#include <math.h>

#define L_DIM 128
#define D_DIM 64
#define M_DIM 256
#define TPB   704
#define NWARP 22

__device__ float g_cenT[D_DIM * M_DIM];   // cen transposed [d][m], original order
__device__ int   g_order[M_DIM];
__device__ int   g_cs[8], g_ce[8];

// ---- packed f32x2 helpers (Blackwell) ----
__device__ __forceinline__ unsigned long long pk2(float lo, float hi) {
    unsigned long long r;
    asm("mov.b64 %0, {%1, %2};" : "=l"(r) : "f"(lo), "f"(hi));
    return r;
}
__device__ __forceinline__ unsigned long long fma2(unsigned long long a,
                                                   unsigned long long b,
                                                   unsigned long long c) {
    unsigned long long d;
    asm("fma.rn.f32x2 %0, %1, %2, %3;" : "=l"(d) : "l"(a), "l"(b), "l"(c));
    return d;
}
__device__ __forceinline__ void upk2(float& lo, float& hi, unsigned long long v) {
    asm("mov.b64 {%0, %1}, %2;" : "=f"(lo), "=f"(hi) : "l"(v));
}
__device__ __forceinline__ int redux_min_s32(int v) {
    int r;
    asm("redux.sync.min.s32 %0, %1, 0xffffffff;" : "=r"(r) : "r"(v));
    return r;
}
union F4U2 { float4 f; unsigned long long u[2]; };

// ---- fused prep: blocks 0..255 compute cen row; block 256 computes order ----
__global__ void prep_kernel(const float* __restrict__ cfeat,
                            const float* __restrict__ conf,
                            const float* __restrict__ W,
                            const float* __restrict__ bias,
                            const int*   __restrict__ cen_c)
{
    __shared__ int cnt[8], base[8];
    const int tid = threadIdx.x;
    if (blockIdx.x == M_DIM) {
        // counting sort of centroids by batch id (ids are NOT sorted)
        if (tid < 8) cnt[tid] = 0;
        __syncthreads();
        const int b = cen_c[4 * tid];
        atomicAdd(&cnt[b], 1);
        __syncthreads();
        if (tid == 0) {
            int a = 0;
            for (int bb = 0; bb < 8; bb++) {
                base[bb] = a; g_cs[bb] = a; a += cnt[bb]; g_ce[bb] = a;
            }
        }
        __syncthreads();
        g_order[atomicAdd(&base[b], 1)] = tid;
    } else if (tid < D_DIM) {
        const int m = blockIdx.x, d = tid;
        const float* row = cfeat + m * L_DIM;
        float acc = bias[d];
#pragma unroll 8
        for (int k = 0; k < L_DIM; k++)
            acc = fmaf(row[k], W[k * D_DIM + d], acc);
        g_cenT[d * M_DIM + m] = conf[m] * acc;
    }
}

__global__ __launch_bounds__(TPB, 1)
void main_kernel(const int*   __restrict__ clu_c,
                 const int*   __restrict__ cen_c,
                 const float* __restrict__ feats,
                 const float* __restrict__ bias,
                 const float* __restrict__ Wg,
                 float*       __restrict__ out,
                 int N, int numGroups)
{
    extern __shared__ float sm[];
    float*  Wd      = sm;                           // 16384: (wx,wx,wy,wy) per (k,lane)
    float2* cen2    = (float2*)(Wd + 4*L_DIM*32);   // 32 x 256 float2 = 16384 floats
    float*  b_s     = (float*)(cen2 + 32 * M_DIM);  // 64
    float*  feats_s = b_s + D_DIM;                  // 22 * 512 = 11264
    float*  clu_s   = feats_s + NWARP * 4 * L_DIM;  // 22 * 256 = 5632
    float*  vbuf    = clu_s + NWARP * 4 * D_DIM;    // 22 * 256 = 5632
    int4*   cm4_s   = (int4*)(vbuf + NWARP * M_DIM);// 256 int4 (permuted)
    int*    ord_s   = (int*)(cm4_s + M_DIM);        // 256
    int*    cs_s    = ord_s + M_DIM;                // 8
    int*    ce_s    = cs_s + 8;                     // 8
    int*    rmeta   = ce_s + 8;                     // 22 * 20

    const int tid  = threadIdx.x;
    const int warp = tid >> 5;
    const int lane = tid & 31;

    // ---- one-time staging (only block-barrier region) ----
    if (tid < M_DIM) ord_s[tid] = g_order[tid];
    if (tid < 8) { cs_s[tid] = g_cs[tid]; ce_s[tid] = g_ce[tid]; }
    if (tid < D_DIM) b_s[tid] = bias[tid];
    // W duplicated pairs: Wd[k*32+ln] = (wx,wx,wy,wy)
    for (int i = tid; i < L_DIM * 32; i += TPB) {
        const int k = i >> 5, ln = i & 31;
        const float2 w2 = *(const float2*)(Wg + k * D_DIM + 2 * ln);
        ((float4*)Wd)[i] = make_float4(w2.x, w2.x, w2.y, w2.y);
    }
    __syncthreads();   // ord_s ready
    // cen2[d2*M + j] = (cen[2*d2][ord[j]], cen[2*d2+1][ord[j]])
    for (int i = tid; i < 32 * M_DIM; i += TPB) {
        const int d2 = i >> 8, j = i & 255;
        cen2[i] = make_float2(g_cenT[(2*d2  )*M_DIM + ord_s[j]],
                              g_cenT[(2*d2+1)*M_DIM + ord_s[j]]);
    }
    if (tid < M_DIM) {
        int4 c = ((const int4*)cen_c)[ord_s[tid]];
        cm4_s[tid] = make_int4(c.y, c.z, c.w, c.y*c.y + c.z*c.z + c.w*c.w);
    }
    __syncthreads();

    // per-warp private slices
    float* fw = feats_s + warp * (4 * L_DIM);   // quad-interleaved [k][4rows]
    float* cw = clu_s   + warp * (4 * D_DIM);
    float* vb = vbuf    + warp * M_DIM;
    int*   mw = rmeta   + warp * 20;            // rb[4], rx[4], ry[4], rz[4], rn2[4]

    const int stride = gridDim.x * NWARP;
    int g = blockIdx.x * NWARP + warp;

    // ---- prologue: prefetch first group into registers ----
    float4 fv0, fv1, fv2, fv3;
    int4   pc4;  int pcv = 0;
    {
        const float4 z = make_float4(0.f, 0.f, 0.f, 0.f);
        fv0 = fv1 = fv2 = fv3 = z;
        if (g < numGroups) {
            const long long r0 = (long long)g * 4;
            if (r0   < N) fv0 = *(const float4*)(feats + (r0  )*L_DIM + lane*4);
            if (r0+1 < N) fv1 = *(const float4*)(feats + (r0+1)*L_DIM + lane*4);
            if (r0+2 < N) fv2 = *(const float4*)(feats + (r0+2)*L_DIM + lane*4);
            if (r0+3 < N) fv3 = *(const float4*)(feats + (r0+3)*L_DIM + lane*4);
            if (lane < 4 && r0 + lane < N) {
                pc4 = ((const int4*)clu_c)[r0 + lane];
                pcv = 1;
            }
        }
    }

    // ---- warp-autonomous pipelined group loop ----
    for (; g < numGroups; g += stride) {
        const int row0 = g * 4;

        // commit current prefetch to smem
        if (lane < 4) {
            if (pcv) {
                mw[lane]      = pc4.x;
                mw[4 + lane]  = pc4.y;
                mw[8 + lane]  = pc4.z;
                mw[12 + lane] = pc4.w;
                mw[16 + lane] = pc4.y*pc4.y + pc4.z*pc4.z + pc4.w*pc4.w;
            } else mw[lane] = -1;
        }
        {   // quad-interleave: fwq[k] = (r0[k], r1[k], r2[k], r3[k])
            float4* fq = (float4*)fw;
            fq[4*lane+0] = make_float4(fv0.x, fv1.x, fv2.x, fv3.x);
            fq[4*lane+1] = make_float4(fv0.y, fv1.y, fv2.y, fv3.y);
            fq[4*lane+2] = make_float4(fv0.z, fv1.z, fv2.z, fv3.z);
            fq[4*lane+3] = make_float4(fv0.w, fv1.w, fv2.w, fv3.w);
        }
        __syncwarp();

        // issue prefetch for NEXT group (overlaps phases A+B)
        {
            const int gn = g + stride;
            const float4 z = make_float4(0.f, 0.f, 0.f, 0.f);
            fv0 = fv1 = fv2 = fv3 = z;
            pcv = 0;
            if (gn < numGroups) {
                const long long r0 = (long long)gn * 4;
                if (r0   < N) fv0 = *(const float4*)(feats + (r0  )*L_DIM + lane*4);
                if (r0+1 < N) fv1 = *(const float4*)(feats + (r0+1)*L_DIM + lane*4);
                if (r0+2 < N) fv2 = *(const float4*)(feats + (r0+2)*L_DIM + lane*4);
                if (r0+3 < N) fv3 = *(const float4*)(feats + (r0+3)*L_DIM + lane*4);
                if (lane < 4 && r0 + lane < N) {
                    pc4 = ((const int4*)clu_c)[r0 + lane];
                    pcv = 1;
                }
            }
        }

        // ---- Phase A (f32x2, pre-duplicated W): lane -> cols 2lane,2lane+1 ----
        float sc0, sc1, sc2, sc3;
        {
            const float bx = b_s[2*lane], by = b_s[2*lane+1];
            unsigned long long acc01x = pk2(bx, bx);
            unsigned long long acc01y = pk2(by, by);
            unsigned long long acc23x = pk2(bx, bx);
            unsigned long long acc23y = pk2(by, by);
            const float4* fq = (const float4*)fw;
            const float4* wq = (const float4*)Wd + lane;
#pragma unroll 4
            for (int k = 0; k < L_DIM; k++) {
                F4U2 xq; xq.f = fq[k];                  // broadcast
                F4U2 wd; wd.f = wq[k*32];               // (wx,wx,wy,wy), conflict-free
                acc01x = fma2(xq.u[0], wd.u[0], acc01x);
                acc01y = fma2(xq.u[0], wd.u[1], acc01y);
                acc23x = fma2(xq.u[1], wd.u[0], acc23x);
                acc23y = fma2(xq.u[1], wd.u[1], acc23y);
            }
            float a0x, a1x, a0y, a1y, a2x, a3x, a2y, a3y;
            upk2(a0x, a1x, acc01x); upk2(a0y, a1y, acc01y);
            upk2(a2x, a3x, acc23x); upk2(a2y, a3y, acc23y);

            float* c0 = cw + 2*lane;
            *(float2*)(c0)             = make_float2(a0x, a0y);
            *(float2*)(c0 +   D_DIM)   = make_float2(a1x, a1y);
            *(float2*)(c0 + 2*D_DIM)   = make_float2(a2x, a2y);
            *(float2*)(c0 + 3*D_DIM)   = make_float2(a3x, a3y);

            float q0 = a0x*a0x + a0y*a0y;
            float q1 = a1x*a1x + a1y*a1y;
            float q2 = a2x*a2x + a2y*a2y;
            float q3 = a3x*a3x + a3y*a3y;
#pragma unroll
            for (int off = 16; off; off >>= 1) {
                q0 += __shfl_xor_sync(0xffffffffu, q0, off);
                q1 += __shfl_xor_sync(0xffffffffu, q1, off);
                q2 += __shfl_xor_sync(0xffffffffu, q2, off);
                q3 += __shfl_xor_sync(0xffffffffu, q3, off);
            }
            sc0 = 1.0f / fmaxf(sqrtf(q0), 1e-12f);
            sc1 = 1.0f / fmaxf(sqrtf(q1), 1e-12f);
            sc2 = 1.0f / fmaxf(sqrtf(q2), 1e-12f);
            sc3 = 1.0f / fmaxf(sqrtf(q3), 1e-12f);
        }
        __syncwarp();

        // ---- Phase B: per row; full row built in per-warp smem buffer ----
#pragma unroll 1
        for (int rr = 0; rr < 4; rr++) {
            const int row = row0 + rr;
            if (row >= N) continue;
            const int rb = mw[rr];
            const int s = cs_s[rb], e = ce_s[rb];
            const int rx = mw[4+rr], ry = mw[8+rr], rz = mw[12+rr], rn2 = mw[16+rr];
            const float* cr = cw + rr * D_DIM;
            const float scale = rr == 0 ? sc0 : rr == 1 ? sc1 : rr == 2 ? sc2 : sc3;

            // zero the row buffer
            {
                const float4 z = make_float4(0.f, 0.f, 0.f, 0.f);
                *(float4*)(vb + lane*4)       = z;
                *(float4*)(vb + 128 + lane*4) = z;
            }
            __syncwarp();

            float sumv = 0.f;
            if (rb >= 0 && e > s) {
                const int nc = (e - s + 31) >> 5;

                // pass 1: pure-integer min of squared distance + redux
                int best = 0x7fffffff;
#pragma unroll 1
                for (int c = 0; c < nc; c++) {
                    const int jj = s + (c << 5) + lane;
                    const int j = (jj < e) ? jj : s;
                    const int4 cm = cm4_s[j];
                    const int d2 = rn2 + cm.w - 2*(rx*cm.x + ry*cm.y + rz*cm.z);
                    if (jj < e) best = min(best, d2);
                }
                best = redux_min_s32(best);
                const float dmin = fmaxf(sqrtf((float)best), 0.1f);  // = -max logit

                // pass 2: f32x2 dot + exp, scatter v*e into row buffer, sum
#pragma unroll 1
                for (int c = 0; c < nc; c++) {
                    const int jj = s + (c << 5) + lane;
                    const bool val = jj < e;
                    const int j = val ? jj : s;
                    unsigned long long v01 = 0ull, v23 = 0ull;
#pragma unroll 4
                    for (int i = 0; i < 16; i++) {
                        F4U2 a; a.f = *(const float4*)(cr + 4*i);            // broadcast
                        const unsigned long long cl =
                            *(const unsigned long long*)(cen2 + (2*i  )*M_DIM + j);
                        const unsigned long long ch =
                            *(const unsigned long long*)(cen2 + (2*i+1)*M_DIM + j);
                        v01 = fma2(a.u[0], cl, v01);
                        v23 = fma2(a.u[1], ch, v23);
                    }
                    float vl0, vl1, vh0, vh1;
                    upk2(vl0, vl1, v01); upk2(vh0, vh1, v23);
                    const float v = (vl0 + vl1) + (vh0 + vh1);

                    const int4 cm = cm4_s[j];
                    const int d2 = rn2 + cm.w - 2*(rx*cm.x + ry*cm.y + rz*cm.z);
                    const float dist = fmaxf(sqrtf((float)d2), 0.1f);
                    const float ee = val ? __expf(dmin - dist) : 0.f;
                    if (val) vb[ord_s[jj]] = v * ee;
                    sumv += ee;
                }
#pragma unroll
                for (int off = 16; off; off >>= 1)
                    sumv += __shfl_xor_sync(0xffffffffu, sumv, off);
            }
            __syncwarp();

            // coalesced full-row write (empty batch -> zeros)
            const float rinv = (sumv > 0.f) ? (scale / sumv) : 0.f;
            float* orow = out + (long long)row * M_DIM;
            float4 o0 = *(const float4*)(vb + lane*4);
            float4 o1 = *(const float4*)(vb + 128 + lane*4);
            o0.x *= rinv; o0.y *= rinv; o0.z *= rinv; o0.w *= rinv;
            o1.x *= rinv; o1.y *= rinv; o1.z *= rinv; o1.w *= rinv;
            *(float4*)(orow + lane*4)       = o0;
            *(float4*)(orow + 128 + lane*4) = o1;
            __syncwarp();   // vb reuse for next row
        }
        // no block barrier: everything in the loop is warp-private
    }
}

extern "C" void kernel_launch(void* const* d_in, const int* in_sizes, int n_in,
                              void* d_out, int out_size)
{
    const int*   clu_c = (const int*)  d_in[0];
    const int*   cen_c = (const int*)  d_in[1];
    const float* feats = (const float*)d_in[2];
    const float* cfeat = (const float*)d_in[3];
    const float* conf  = (const float*)d_in[4];
    const float* W     = (const float*)d_in[5];
    const float* bias  = (const float*)d_in[6];
    float* out = (float*)d_out;

    const int N = in_sizes[2] / L_DIM;
    const int numGroups = (N + 3) / 4;

    // smem: floats 16384+16384+64+11264+5632+5632 = 55360
    //     + ints 1024+256+16+440 = 1736   -> 228384 B
    const size_t SMEM = (size_t)(55360 + 1736) * 4;

    prep_kernel<<<M_DIM + 1, 256>>>(cfeat, conf, W, bias, cen_c);

    cudaFuncSetAttribute(main_kernel,
                         cudaFuncAttributeMaxDynamicSharedMemorySize, (int)SMEM);
    main_kernel<<<148, TPB, SMEM>>>(clu_c, cen_c, feats, bias, W, out, N, numGroups);
}

// round 16
// speedup vs baseline: 1.1534x; 1.1534x over previous
#include <cuda_runtime.h>
#include <math.h>

#define L_DIM 128
#define D_DIM 64
#define M_DIM 256
#define TPB   704
#define NWARP 22
#define FQPAD 144   // float4 slots per warp: 128 quads + 16 pad (skew k + k>>3)

__device__ float g_cenT[D_DIM * M_DIM];   // cen transposed [d][m], original order
__device__ int   g_order[M_DIM];
__device__ int   g_cs[8], g_ce[8];

// ---- packed f32x2 helpers (Blackwell) ----
__device__ __forceinline__ unsigned long long pk2(float lo, float hi) {
    unsigned long long r;
    asm("mov.b64 %0, {%1, %2};" : "=l"(r) : "f"(lo), "f"(hi));
    return r;
}
__device__ __forceinline__ unsigned long long fma2(unsigned long long a,
                                                   unsigned long long b,
                                                   unsigned long long c) {
    unsigned long long d;
    asm("fma.rn.f32x2 %0, %1, %2, %3;" : "=l"(d) : "l"(a), "l"(b), "l"(c));
    return d;
}
__device__ __forceinline__ void upk2(float& lo, float& hi, unsigned long long v) {
    asm("mov.b64 {%0, %1}, %2;" : "=f"(lo), "=f"(hi) : "l"(v));
}
__device__ __forceinline__ int redux_min_s32(int v) {
    int r;
    asm("redux.sync.min.s32 %0, %1, 0xffffffff;" : "=r"(r) : "r"(v));
    return r;
}
union F4U2 { float4 f; unsigned long long u[2]; };

// ---- fused prep: blocks 0..255 compute cen row; block 256 computes order ----
__global__ void prep_kernel(const float* __restrict__ cfeat,
                            const float* __restrict__ conf,
                            const float* __restrict__ W,
                            const float* __restrict__ bias,
                            const int*   __restrict__ cen_c)
{
    __shared__ int cnt[8], base[8];
    const int tid = threadIdx.x;
    if (blockIdx.x == M_DIM) {
        // counting sort of centroids by batch id (ids are NOT sorted)
        if (tid < 8) cnt[tid] = 0;
        __syncthreads();
        const int b = cen_c[4 * tid];
        atomicAdd(&cnt[b], 1);
        __syncthreads();
        if (tid == 0) {
            int a = 0;
            for (int bb = 0; bb < 8; bb++) {
                base[bb] = a; g_cs[bb] = a; a += cnt[bb]; g_ce[bb] = a;
            }
        }
        __syncthreads();
        g_order[atomicAdd(&base[b], 1)] = tid;
    } else if (tid < D_DIM) {
        const int m = blockIdx.x, d = tid;
        const float* row = cfeat + m * L_DIM;
        float acc = bias[d];
#pragma unroll 8
        for (int k = 0; k < L_DIM; k++)
            acc = fmaf(row[k], W[k * D_DIM + d], acc);
        g_cenT[d * M_DIM + m] = conf[m] * acc;
    }
}

__global__ __launch_bounds__(TPB, 1)
void main_kernel(const int*   __restrict__ clu_c,
                 const int*   __restrict__ cen_c,
                 const float* __restrict__ feats,
                 const float* __restrict__ bias,
                 const float* __restrict__ Wg,
                 float*       __restrict__ out,
                 int N, int numGroups)
{
    extern __shared__ float sm[];
    float*  W_s     = sm;                           // 8192 (float2 pairs per k,lane)
    float2* cen2    = (float2*)(W_s + L_DIM*D_DIM); // 32 x 256 float2 = 16384 floats
    float*  b_s     = (float*)(cen2 + 32 * M_DIM);  // 64
    float*  feats_s = b_s + D_DIM;                  // 22 * 576 = 12672 (skew-padded)
    float*  clu_s   = feats_s + NWARP * 4 * FQPAD;  // 22 * 256 = 5632
    float*  vbuf    = clu_s + NWARP * 4 * D_DIM;    // 22 * 256 = 5632
    int4*   cm4_s   = (int4*)(vbuf + NWARP * M_DIM);// 256 int4 (permuted)
    int*    ord_s   = (int*)(cm4_s + M_DIM);        // 256
    int*    cs_s    = ord_s + M_DIM;                // 8
    int*    ce_s    = cs_s + 8;                     // 8
    int*    rmeta   = ce_s + 8;                     // 22 * 20

    const int tid  = threadIdx.x;
    const int warp = tid >> 5;
    const int lane = tid & 31;

    // ---- one-time staging (only block-barrier region) ----
    if (tid < M_DIM) ord_s[tid] = g_order[tid];
    if (tid < 8) { cs_s[tid] = g_cs[tid]; ce_s[tid] = g_ce[tid]; }
    if (tid < D_DIM) b_s[tid] = bias[tid];
    for (int i = tid; i < L_DIM * D_DIM; i += TPB) W_s[i] = Wg[i];
    __syncthreads();   // ord_s ready
    // cen2[d2*M + j] = (cen[2*d2][ord[j]], cen[2*d2+1][ord[j]])
    for (int i = tid; i < 32 * M_DIM; i += TPB) {
        const int d2 = i >> 8, j = i & 255;
        cen2[i] = make_float2(g_cenT[(2*d2  )*M_DIM + ord_s[j]],
                              g_cenT[(2*d2+1)*M_DIM + ord_s[j]]);
    }
    if (tid < M_DIM) {
        int4 c = ((const int4*)cen_c)[ord_s[tid]];
        cm4_s[tid] = make_int4(c.y, c.z, c.w, c.y*c.y + c.z*c.z + c.w*c.w);
    }
    __syncthreads();

    // per-warp private slices
    float* fw = feats_s + warp * (4 * FQPAD);   // skew-padded quads [k + (k>>3)]
    float* cw = clu_s   + warp * (4 * D_DIM);
    float* vb = vbuf    + warp * M_DIM;
    int*   mw = rmeta   + warp * 20;            // rb[4], rx[4], ry[4], rz[4], rn2[4]

    const int stride = gridDim.x * NWARP;
    int g = blockIdx.x * NWARP + warp;

    // ---- prologue: prefetch first group into registers ----
    float4 fv0, fv1, fv2, fv3;
    int4   pc4;  int pcv = 0;
    {
        const float4 z = make_float4(0.f, 0.f, 0.f, 0.f);
        fv0 = fv1 = fv2 = fv3 = z;
        if (g < numGroups) {
            const long long r0 = (long long)g * 4;
            if (r0   < N) fv0 = *(const float4*)(feats + (r0  )*L_DIM + lane*4);
            if (r0+1 < N) fv1 = *(const float4*)(feats + (r0+1)*L_DIM + lane*4);
            if (r0+2 < N) fv2 = *(const float4*)(feats + (r0+2)*L_DIM + lane*4);
            if (r0+3 < N) fv3 = *(const float4*)(feats + (r0+3)*L_DIM + lane*4);
            if (lane < 4 && r0 + lane < N) {
                pc4 = ((const int4*)clu_c)[r0 + lane];
                pcv = 1;
            }
        }
    }

    // ---- warp-autonomous pipelined group loop ----
    for (; g < numGroups; g += stride) {
        const int row0 = g * 4;

        // commit current prefetch to smem
        if (lane < 4) {
            if (pcv) {
                mw[lane]      = pc4.x;
                mw[4 + lane]  = pc4.y;
                mw[8 + lane]  = pc4.z;
                mw[12 + lane] = pc4.w;
                mw[16 + lane] = pc4.y*pc4.y + pc4.z*pc4.z + pc4.w*pc4.w;
            } else mw[lane] = -1;
        }
        {   // skew-padded quad store: quad for k at fq[k + (k>>3)]
            // lane owns k = 4*lane..4*lane+3 -> base 4*lane + (lane>>1)
            float4* fq = (float4*)fw + 4*lane + (lane >> 1);
            fq[0] = make_float4(fv0.x, fv1.x, fv2.x, fv3.x);
            fq[1] = make_float4(fv0.y, fv1.y, fv2.y, fv3.y);
            fq[2] = make_float4(fv0.z, fv1.z, fv2.z, fv3.z);
            fq[3] = make_float4(fv0.w, fv1.w, fv2.w, fv3.w);
        }
        __syncwarp();

        // issue prefetch for NEXT group (overlaps phases A+B)
        {
            const int gn = g + stride;
            const float4 z = make_float4(0.f, 0.f, 0.f, 0.f);
            fv0 = fv1 = fv2 = fv3 = z;
            pcv = 0;
            if (gn < numGroups) {
                const long long r0 = (long long)gn * 4;
                if (r0   < N) fv0 = *(const float4*)(feats + (r0  )*L_DIM + lane*4);
                if (r0+1 < N) fv1 = *(const float4*)(feats + (r0+1)*L_DIM + lane*4);
                if (r0+2 < N) fv2 = *(const float4*)(feats + (r0+2)*L_DIM + lane*4);
                if (r0+3 < N) fv3 = *(const float4*)(feats + (r0+3)*L_DIM + lane*4);
                if (lane < 4 && r0 + lane < N) {
                    pc4 = ((const int4*)clu_c)[r0 + lane];
                    pcv = 1;
                }
            }
        }

        // ---- Phase A (f32x2): lane -> cols 2lane,2lane+1; pairs over rows ----
        float sc0, sc1, sc2, sc3;
        {
            const float bx = b_s[2*lane], by = b_s[2*lane+1];
            unsigned long long acc01x = pk2(bx, bx);
            unsigned long long acc01y = pk2(by, by);
            unsigned long long acc23x = pk2(bx, bx);
            unsigned long long acc23y = pk2(by, by);
            const float4* fq = (const float4*)fw;
#pragma unroll 2
            for (int m8 = 0; m8 < 16; m8++) {       // 8 k per block, skew +1/block
                const float4* fm = fq + 9 * m8;
#pragma unroll
                for (int kk = 0; kk < 8; kk++) {
                    const int k = 8*m8 + kk;
                    F4U2 xq; xq.f = fm[kk];                           // broadcast
                    const float2 w2 = *(const float2*)(W_s + k*D_DIM + 2*lane);
                    const unsigned long long wxx = pk2(w2.x, w2.x);
                    const unsigned long long wyy = pk2(w2.y, w2.y);
                    acc01x = fma2(xq.u[0], wxx, acc01x);
                    acc01y = fma2(xq.u[0], wyy, acc01y);
                    acc23x = fma2(xq.u[1], wxx, acc23x);
                    acc23y = fma2(xq.u[1], wyy, acc23y);
                }
            }
            float a0x, a1x, a0y, a1y, a2x, a3x, a2y, a3y;
            upk2(a0x, a1x, acc01x); upk2(a0y, a1y, acc01y);
            upk2(a2x, a3x, acc23x); upk2(a2y, a3y, acc23y);

            float* c0 = cw + 2*lane;
            *(float2*)(c0)             = make_float2(a0x, a0y);
            *(float2*)(c0 +   D_DIM)   = make_float2(a1x, a1y);
            *(float2*)(c0 + 2*D_DIM)   = make_float2(a2x, a2y);
            *(float2*)(c0 + 3*D_DIM)   = make_float2(a3x, a3y);

            float q0 = a0x*a0x + a0y*a0y;
            float q1 = a1x*a1x + a1y*a1y;
            float q2 = a2x*a2x + a2y*a2y;
            float q3 = a3x*a3x + a3y*a3y;
#pragma unroll
            for (int off = 16; off; off >>= 1) {
                q0 += __shfl_xor_sync(0xffffffffu, q0, off);
                q1 += __shfl_xor_sync(0xffffffffu, q1, off);
                q2 += __shfl_xor_sync(0xffffffffu, q2, off);
                q3 += __shfl_xor_sync(0xffffffffu, q3, off);
            }
            sc0 = 1.0f / fmaxf(sqrtf(q0), 1e-12f);
            sc1 = 1.0f / fmaxf(sqrtf(q1), 1e-12f);
            sc2 = 1.0f / fmaxf(sqrtf(q2), 1e-12f);
            sc3 = 1.0f / fmaxf(sqrtf(q3), 1e-12f);
        }
        __syncwarp();

        // ---- Phase B: per row; full row built in per-warp smem buffer ----
#pragma unroll 1
        for (int rr = 0; rr < 4; rr++) {
            const int row = row0 + rr;
            if (row >= N) continue;
            const int rb = mw[rr];
            const int s = cs_s[rb], e = ce_s[rb];
            const int rx = mw[4+rr], ry = mw[8+rr], rz = mw[12+rr], rn2 = mw[16+rr];
            const float* cr = cw + rr * D_DIM;
            const float scale = rr == 0 ? sc0 : rr == 1 ? sc1 : rr == 2 ? sc2 : sc3;

            // zero the row buffer
            {
                const float4 z = make_float4(0.f, 0.f, 0.f, 0.f);
                *(float4*)(vb + lane*4)       = z;
                *(float4*)(vb + 128 + lane*4) = z;
            }
            __syncwarp();

            float sumv = 0.f;
            if (rb >= 0 && e > s) {
                const int nc = (e - s + 31) >> 5;

                // pass 1: pure-integer min of squared distance + redux
                int best = 0x7fffffff;
#pragma unroll 1
                for (int c = 0; c < nc; c++) {
                    const int jj = s + (c << 5) + lane;
                    const int j = (jj < e) ? jj : s;
                    const int4 cm = cm4_s[j];
                    const int d2 = rn2 + cm.w - 2*(rx*cm.x + ry*cm.y + rz*cm.z);
                    if (jj < e) best = min(best, d2);
                }
                best = redux_min_s32(best);
                const float dmin = fmaxf(sqrtf((float)best), 0.1f);  // = -max logit

                // pass 2: f32x2 dot + exp, scatter v*e into row buffer, sum
#pragma unroll 1
                for (int c = 0; c < nc; c++) {
                    const int jj = s + (c << 5) + lane;
                    const bool val = jj < e;
                    const int j = val ? jj : s;
                    unsigned long long v01 = 0ull, v23 = 0ull;
#pragma unroll 4
                    for (int i = 0; i < 16; i++) {
                        F4U2 a; a.f = *(const float4*)(cr + 4*i);            // broadcast
                        const unsigned long long cl =
                            *(const unsigned long long*)(cen2 + (2*i  )*M_DIM + j);
                        const unsigned long long ch =
                            *(const unsigned long long*)(cen2 + (2*i+1)*M_DIM + j);
                        v01 = fma2(a.u[0], cl, v01);
                        v23 = fma2(a.u[1], ch, v23);
                    }
                    float vl0, vl1, vh0, vh1;
                    upk2(vl0, vl1, v01); upk2(vh0, vh1, v23);
                    const float v = (vl0 + vl1) + (vh0 + vh1);

                    const int4 cm = cm4_s[j];
                    const int d2 = rn2 + cm.w - 2*(rx*cm.x + ry*cm.y + rz*cm.z);
                    const float dist = fmaxf(sqrtf((float)d2), 0.1f);
                    const float ee = val ? __expf(dmin - dist) : 0.f;
                    if (val) vb[ord_s[jj]] = v * ee;
                    sumv += ee;
                }
#pragma unroll
                for (int off = 16; off; off >>= 1)
                    sumv += __shfl_xor_sync(0xffffffffu, sumv, off);
            }
            __syncwarp();

            // coalesced full-row write (empty batch -> zeros)
            const float rinv = (sumv > 0.f) ? (scale / sumv) : 0.f;
            float* orow = out + (long long)row * M_DIM;
            float4 o0 = *(const float4*)(vb + lane*4);
            float4 o1 = *(const float4*)(vb + 128 + lane*4);
            o0.x *= rinv; o0.y *= rinv; o0.z *= rinv; o0.w *= rinv;
            o1.x *= rinv; o1.y *= rinv; o1.z *= rinv; o1.w *= rinv;
            *(float4*)(orow + lane*4)       = o0;
            *(float4*)(orow + 128 + lane*4) = o1;
            __syncwarp();   // vb reuse for next row
        }
        // no block barrier: everything in the loop is warp-private
    }
}

extern "C" void kernel_launch(void* const* d_in, const int* in_sizes, int n_in,
                              void* d_out, int out_size)
{
    const int*   clu_c = (const int*)  d_in[0];
    const int*   cen_c = (const int*)  d_in[1];
    const float* feats = (const float*)d_in[2];
    const float* cfeat = (const float*)d_in[3];
    const float* conf  = (const float*)d_in[4];
    const float* W     = (const float*)d_in[5];
    const float* bias  = (const float*)d_in[6];
    float* out = (float*)d_out;

    const int N = in_sizes[2] / L_DIM;
    const int numGroups = (N + 3) / 4;

    // smem: floats 8192+16384+64+12672+5632+5632 = 48576
    //     + ints 1024+256+16+440 = 1736   -> 201248 B
    const size_t SMEM = (size_t)(48576 + 1736) * 4;

    prep_kernel<<<M_DIM + 1, 256>>>(cfeat, conf, W, bias, cen_c);

    cudaFuncSetAttribute(main_kernel,
                         cudaFuncAttributeMaxDynamicSharedMemorySize, (int)SMEM);
    main_kernel<<<148, TPB, SMEM>>>(clu_c, cen_c, feats, bias, W, out, N, numGroups);
}